// round 1
// baseline (speedup 1.0000x reference)
#include <cuda_runtime.h>
#include <math.h>

#define BB 128
#define TT 512
#define FF 16
#define HH 32

// ---------------- scratch (device globals; no runtime allocation) ----------------
__device__ float d_xpe[BB * TT * 48];                      // encoder input proj   12.6 MB
__device__ float d_h  [BB * TT * FF];                      // encoder output        4.2 MB
__device__ float d_u1 [(size_t)FF * BB * TT * 64];         // biGRU output        268 MB
__device__ float d_xp2[(size_t)FF * BB * TT * 96];         // g2 input proj       402 MB
__device__ float d_v2 [(size_t)FF * BB * TT * 32];         // g2 output           134 MB
__device__ float d_a3 [(size_t)FF * BB * TT * 64];         // conv3 output        268 MB
__device__ float d_a2 [(size_t)FF * BB * TT * 128];        // conv2 output        512 MB

__device__ __forceinline__ float sigmoidf_(float x) {
    return 1.0f / (1.0f + __expf(-x));
}
__device__ __forceinline__ float tanhf_(float x) {
    float ax = fabsf(x);
    float e  = __expf(-2.0f * ax);
    float t  = (1.0f - e) / (1.0f + e);
    return copysignf(t, x);
}
__device__ __forceinline__ float leaky_(float v) {
    return v >= 0.0f ? v : 0.01f * v;
}

// ---------------- kernel 0: encoder input projection ----------------
// xpe[b][t][g] = x[b][0][t]*Wih[g][0] + x[b][1][t]*Wih[g][1] + bih[g]
__global__ void k_enc_xp(const float* __restrict__ x,
                         const float* __restrict__ Wih,
                         const float* __restrict__ bih) {
    int idx = blockIdx.x * blockDim.x + threadIdx.x;
    if (idx >= BB * TT * 48) return;
    int g  = idx % 48;
    int bt = idx / 48;
    int b  = bt / TT;
    int t  = bt % TT;
    float x0 = x[b * 2 * TT + t];
    float x1 = x[b * 2 * TT + TT + t];
    d_xpe[idx] = x0 * Wih[g * 2] + x1 * Wih[g * 2 + 1] + bih[g];
}

// ---------------- kernel 1: encoder GRU recurrence (hidden=16) ----------------
// one warp per batch; lane l owns gate-rows l (r/z over 0..31) and 32+l (n, l<16)
__global__ void k_enc_rec(const float* __restrict__ Whh,
                          const float* __restrict__ bhh) {
    int warp = (blockIdx.x * blockDim.x + threadIdx.x) >> 5;
    int l    = threadIdx.x & 31;
    if (warp >= BB) return;
    int b = warp;

    float w0[16], w1[16];
#pragma unroll
    for (int k = 0; k < 16; k++) {
        w0[k] = Whh[l * 16 + k];
        w1[k] = (l < 16) ? Whh[(32 + l) * 16 + k] : 0.0f;
    }
    float bh0 = bhh[l];
    float bh1 = (l < 16) ? bhh[32 + l] : 0.0f;

    float h = 0.0f;
    const float* xp = d_xpe + (size_t)b * TT * 48;
    float* ho = d_h + (size_t)b * TT * FF;

    for (int t = 0; t < TT; t++) {
        float xpa = xp[t * 48 + l];
        float xpn = (l < 16) ? xp[t * 48 + 32 + l] : 0.0f;
        float a0 = bh0, a1 = bh1;
#pragma unroll
        for (int k = 0; k < 16; k++) {
            float hk = __shfl_sync(0xffffffffu, h, k);
            a0 += hk * w0[k];
            a1 += hk * w1[k];
        }
        float g = sigmoidf_(xpa + a0);                   // l<16: r, l>=16: z
        float z = __shfl_sync(0xffffffffu, g, l + 16);   // valid for l<16
        if (l < 16) {
            float n = tanhf_(xpn + g * a1);
            h = (1.0f - z) * n + z * h;
            ho[t * FF + l] = h;
        }
    }
}

// ---------------- kernel 2: per-feature bidirectional GRU (input=1, hidden=32) ----------------
// one warp per (dir,f,b). Whh rows in registers. Input is a scalar -> proj in-loop.
__global__ __launch_bounds__(256) void k_g1(
    const float* __restrict__ Wih_f, const float* __restrict__ Whh_f,
    const float* __restrict__ bih_f, const float* __restrict__ bhh_f,
    const float* __restrict__ Wih_b, const float* __restrict__ Whh_b,
    const float* __restrict__ bih_b, const float* __restrict__ bhh_b) {
    int gw = (blockIdx.x * 256 + threadIdx.x) >> 5;   // 0..4095
    int l  = threadIdx.x & 31;
    int b   = gw & (BB - 1);
    int f   = (gw >> 7) & (FF - 1);
    int dir = gw >> 11;

    const float* Wih = dir ? Wih_b : Wih_f;
    const float* Whh = dir ? Whh_b : Whh_f;
    const float* bih = dir ? bih_b : bih_f;
    const float* bhh = dir ? bhh_b : bhh_f;

    float wr[32], wz[32], wn[32];
    const float* Wr = Whh + (size_t)(f * 96 + l) * 32;
    const float* Wz = Whh + (size_t)(f * 96 + 32 + l) * 32;
    const float* Wn = Whh + (size_t)(f * 96 + 64 + l) * 32;
#pragma unroll
    for (int k = 0; k < 32; k++) { wr[k] = Wr[k]; wz[k] = Wz[k]; wn[k] = Wn[k]; }

    float wir = Wih[f * 96 + l], wiz = Wih[f * 96 + 32 + l], win = Wih[f * 96 + 64 + l];
    float br  = bih[f * 96 + l], bz  = bih[f * 96 + 32 + l], bn  = bih[f * 96 + 64 + l];
    float cr  = bhh[f * 96 + l], cz  = bhh[f * 96 + 32 + l], cn  = bhh[f * 96 + 64 + l];

    float h = 0.0f;
    const float* hin = d_h + (size_t)b * TT * FF + f;
    float* u = d_u1 + (size_t)(f * BB + b) * TT * 64 + dir * 32 + l;

    for (int s = 0; s < TT; s++) {
        int t = dir ? (TT - 1 - s) : s;
        float xi = hin[(size_t)t * FF];
        float ar = cr, az = cz, an = cn;
#pragma unroll
        for (int k = 0; k < 32; k++) {
            float hk = __shfl_sync(0xffffffffu, h, k);
            ar += hk * wr[k];
            az += hk * wz[k];
            an += hk * wn[k];
        }
        float r = sigmoidf_(xi * wir + br + ar);
        float z = sigmoidf_(xi * wiz + bz + az);
        float n = tanhf_(xi * win + bn + r * an);
        h = (1.0f - z) * n + z * h;
        u[(size_t)t * 64] = h;
    }
}

// ---------------- kernel 3: g2 input projection GEMM ----------------
// xp2[f][r][j] = sum_i u1[f][r][i] * Wih2[f][j][i] + bih2[f][j]   (r = b*T+t, K=64, N=96)
__global__ __launch_bounds__(256) void k_xp2(const float* __restrict__ Wih2,
                                             const float* __restrict__ bih2) {
    __shared__ float sA[64][65];
    __shared__ float sB[64][97];   // transposed: sB[k][j]
    int f  = blockIdx.y;
    int r0 = blockIdx.x * 64;
    int tid = threadIdx.x;

    const float* A  = d_u1 + (size_t)f * BB * TT * 64;
    const float* Wb = Wih2 + (size_t)f * 96 * 64;

    for (int i = tid; i < 64 * 64; i += 256) {
        int rr = i >> 6, kk = i & 63;
        sA[rr][kk] = A[(size_t)(r0 + rr) * 64 + kk];
    }
    for (int i = tid; i < 96 * 64; i += 256) {
        int j = i >> 6, kk = i & 63;
        sB[kk][j] = Wb[i];
    }
    __syncthreads();

    int tj = tid & 15;   // col group: j0 = tj*6
    int tr = tid >> 4;   // row group: r = tr*4
    float acc[4][6];
#pragma unroll
    for (int a = 0; a < 4; a++)
#pragma unroll
        for (int c = 0; c < 6; c++) acc[a][c] = bih2[f * 96 + tj * 6 + c];

    for (int k = 0; k < 64; k++) {
        float av[4], bv[6];
#pragma unroll
        for (int a = 0; a < 4; a++) av[a] = sA[tr * 4 + a][k];
#pragma unroll
        for (int c = 0; c < 6; c++) bv[c] = sB[k][tj * 6 + c];
#pragma unroll
        for (int a = 0; a < 4; a++)
#pragma unroll
            for (int c = 0; c < 6; c++) acc[a][c] += av[a] * bv[c];
    }

    // stage through smem for coalesced writeback
    __syncthreads();
    float* so = &sB[0][0];
#pragma unroll
    for (int a = 0; a < 4; a++)
#pragma unroll
        for (int c = 0; c < 6; c++) so[(tr * 4 + a) * 96 + tj * 6 + c] = acc[a][c];
    __syncthreads();
    float* C = d_xp2 + (size_t)f * BB * TT * 96 + (size_t)r0 * 96;
    for (int i = tid; i < 64 * 96; i += 256) C[i] = so[i];
}

// ---------------- kernel 4: g2 GRU recurrence (input proj precomputed) ----------------
__global__ __launch_bounds__(256) void k_g2(const float* __restrict__ Whh2,
                                            const float* __restrict__ bhh2) {
    int gw = (blockIdx.x * 256 + threadIdx.x) >> 5;   // 0..2047
    int l  = threadIdx.x & 31;
    int b = gw & (BB - 1);
    int f = gw >> 7;

    float wr[32], wz[32], wn[32];
    const float* Wr = Whh2 + (size_t)(f * 96 + l) * 32;
    const float* Wz = Whh2 + (size_t)(f * 96 + 32 + l) * 32;
    const float* Wn = Whh2 + (size_t)(f * 96 + 64 + l) * 32;
#pragma unroll
    for (int k = 0; k < 32; k++) { wr[k] = Wr[k]; wz[k] = Wz[k]; wn[k] = Wn[k]; }
    float cr = bhh2[f * 96 + l], cz = bhh2[f * 96 + 32 + l], cn = bhh2[f * 96 + 64 + l];

    float h = 0.0f;
    const float* XP = d_xp2 + ((size_t)f * BB + b) * TT * 96;
    float* V = d_v2 + ((size_t)f * BB + b) * TT * 32 + l;

    for (int t = 0; t < TT; t++) {
        const float* xt = XP + (size_t)t * 96;
        float xr = xt[l], xz = xt[32 + l], xn = xt[64 + l];
        float ar = cr, az = cz, an = cn;
#pragma unroll
        for (int k = 0; k < 32; k++) {
            float hk = __shfl_sync(0xffffffffu, h, k);
            ar += hk * wr[k];
            az += hk * wz[k];
            an += hk * wn[k];
        }
        float r = sigmoidf_(xr + ar);
        float z = sigmoidf_(xz + az);
        float n = tanhf_(xn + r * an);
        h = (1.0f - z) * n + z * h;
        V[(size_t)t * 32] = h;
    }
}

// ---------------- kernel 5: convT 32 -> 64 + leaky ----------------
// y[co][t] = sum_{ci,j} x[ci][t+j-2] * w3[f][ci][co][4-j] + b3[f][co]
__global__ __launch_bounds__(256) void k_conv3(const float* __restrict__ w3,
                                               const float* __restrict__ b3) {
    __shared__ float sx[32][73];       // [ci][tt], tt = t - t0 + 2, 68 valid
    __shared__ float sw[16][64 * 5];   // ci-chunk of 16
    int f = blockIdx.z, bb = blockIdx.y, t0 = blockIdx.x * 64;
    int tid = threadIdx.x;

    const float* X = d_v2 + ((size_t)f * BB + bb) * TT * 32;
    for (int i = tid; i < 68 * 32; i += 256) {
        int tt = i >> 5, ci = i & 31;
        int t = t0 - 2 + tt;
        sx[ci][tt] = (t >= 0 && t < TT) ? X[(size_t)t * 32 + ci] : 0.0f;
    }

    int tg = tid & 15;        // t group: t = t0 + tg*4 + dt
    int cg = tid >> 4;        // co group: co = cg*4 + o
    float acc[4][4];
#pragma unroll
    for (int o = 0; o < 4; o++)
#pragma unroll
        for (int dt = 0; dt < 4; dt++) acc[o][dt] = 0.0f;

    for (int cc = 0; cc < 2; cc++) {
        __syncthreads();
        const float* Wsrc = w3 + ((size_t)f * 32 + cc * 16) * 64 * 5;
        for (int i = tid; i < 16 * 320; i += 256) (&sw[0][0])[i] = Wsrc[i];
        __syncthreads();
        for (int ci = 0; ci < 16; ci++) {
            float xv[8];
#pragma unroll
            for (int q = 0; q < 8; q++) xv[q] = sx[cc * 16 + ci][tg * 4 + q];
            float wv[4][5];
#pragma unroll
            for (int o = 0; o < 4; o++)
#pragma unroll
                for (int k = 0; k < 5; k++) wv[o][k] = sw[ci][(cg * 4 + o) * 5 + k];
#pragma unroll
            for (int j = 0; j < 5; j++)
#pragma unroll
                for (int o = 0; o < 4; o++)
#pragma unroll
                    for (int dt = 0; dt < 4; dt++)
                        acc[o][dt] += xv[dt + j] * wv[o][4 - j];
        }
    }

    float* Y = d_a3 + (((size_t)f * BB + bb) * TT + t0) * 64;
#pragma unroll
    for (int dt = 0; dt < 4; dt++) {
        float4 v;
        v.x = leaky_(acc[0][dt] + b3[f * 64 + cg * 4 + 0]);
        v.y = leaky_(acc[1][dt] + b3[f * 64 + cg * 4 + 1]);
        v.z = leaky_(acc[2][dt] + b3[f * 64 + cg * 4 + 2]);
        v.w = leaky_(acc[3][dt] + b3[f * 64 + cg * 4 + 3]);
        *(float4*)&Y[(size_t)(tg * 4 + dt) * 64 + cg * 4] = v;
    }
}

// ---------------- kernel 6: convT 64 -> 128 + leaky ----------------
__global__ __launch_bounds__(256) void k_conv2(const float* __restrict__ w2,
                                               const float* __restrict__ b2) {
    __shared__ float sx[64][73];        // [ci][tt]
    __shared__ float sw[8][128 * 5];    // ci-chunk of 8
    int f = blockIdx.z, bb = blockIdx.y, t0 = blockIdx.x * 64;
    int tid = threadIdx.x;

    const float* X = d_a3 + ((size_t)f * BB + bb) * TT * 64;
    for (int i = tid; i < 68 * 64; i += 256) {
        int tt = i >> 6, ci = i & 63;
        int t = t0 - 2 + tt;
        sx[ci][tt] = (t >= 0 && t < TT) ? X[(size_t)t * 64 + ci] : 0.0f;
    }

    int tg = tid & 15;        // t = t0 + tg*4 + dt
    int cg = tid >> 4;        // co = cg*8 + o
    float acc[8][4];
#pragma unroll
    for (int o = 0; o < 8; o++)
#pragma unroll
        for (int dt = 0; dt < 4; dt++) acc[o][dt] = 0.0f;

    for (int cc = 0; cc < 8; cc++) {
        __syncthreads();
        const float* Wsrc = w2 + ((size_t)f * 64 + cc * 8) * 128 * 5;
        for (int i = tid; i < 8 * 640; i += 256) (&sw[0][0])[i] = Wsrc[i];
        __syncthreads();
        for (int ci = 0; ci < 8; ci++) {
            float xv[8];
#pragma unroll
            for (int q = 0; q < 8; q++) xv[q] = sx[cc * 8 + ci][tg * 4 + q];
            float wv[8][5];
#pragma unroll
            for (int o = 0; o < 8; o++)
#pragma unroll
                for (int k = 0; k < 5; k++) wv[o][k] = sw[ci][(cg * 8 + o) * 5 + k];
#pragma unroll
            for (int j = 0; j < 5; j++)
#pragma unroll
                for (int o = 0; o < 8; o++)
#pragma unroll
                    for (int dt = 0; dt < 4; dt++)
                        acc[o][dt] += xv[dt + j] * wv[o][4 - j];
        }
    }

    float* Y = d_a2 + (((size_t)f * BB + bb) * TT + t0) * 128;
#pragma unroll
    for (int dt = 0; dt < 4; dt++) {
        float4 v0, v1;
        v0.x = leaky_(acc[0][dt] + b2[f * 128 + cg * 8 + 0]);
        v0.y = leaky_(acc[1][dt] + b2[f * 128 + cg * 8 + 1]);
        v0.z = leaky_(acc[2][dt] + b2[f * 128 + cg * 8 + 2]);
        v0.w = leaky_(acc[3][dt] + b2[f * 128 + cg * 8 + 3]);
        v1.x = leaky_(acc[4][dt] + b2[f * 128 + cg * 8 + 4]);
        v1.y = leaky_(acc[5][dt] + b2[f * 128 + cg * 8 + 5]);
        v1.z = leaky_(acc[6][dt] + b2[f * 128 + cg * 8 + 6]);
        v1.w = leaky_(acc[7][dt] + b2[f * 128 + cg * 8 + 7]);
        *(float4*)&Y[(size_t)(tg * 4 + dt) * 128 + cg * 8]     = v0;
        *(float4*)&Y[(size_t)(tg * 4 + dt) * 128 + cg * 8 + 4] = v1;
    }
}

// ---------------- kernel 7: convT 128 -> 1 + leaky, write final output ----------------
__global__ __launch_bounds__(64) void k_conv1(const float* __restrict__ w1,
                                              const float* __restrict__ b1,
                                              float* __restrict__ out) {
    __shared__ float sx[68][132];    // [tt][ci]
    __shared__ float sw[5][128];     // wc[j][ci] = w1[f][ci][0][4-j]
    int f = blockIdx.z, bb = blockIdx.y, t0 = blockIdx.x * 64;
    int tid = threadIdx.x;

    const float* X = d_a2 + ((size_t)f * BB + bb) * TT * 128;
    for (int i = tid; i < 68 * 128; i += 64) {
        int tt = i >> 7, ci = i & 127;
        int t = t0 - 2 + tt;
        sx[tt][ci] = (t >= 0 && t < TT) ? X[(size_t)t * 128 + ci] : 0.0f;
    }
    for (int i = tid; i < 5 * 128; i += 64) {
        int j = i >> 7, ci = i & 127;
        sw[j][ci] = w1[f * 640 + ci * 5 + (4 - j)];
    }
    __syncthreads();

    int tl = tid;   // local t, 0..63
    float a0 = 0.0f, a1 = 0.0f, a2s = 0.0f, a3s = 0.0f;
#pragma unroll
    for (int j = 0; j < 5; j++) {
        const float* xr = &sx[tl + j][0];
        const float* wr_ = &sw[j][0];
#pragma unroll
        for (int ci = 0; ci < 128; ci += 4) {
            float4 a = *(const float4*)&xr[ci];
            float4 w = *(const float4*)&wr_[ci];
            a0 += a.x * w.x;
            a1 += a.y * w.y;
            a2s += a.z * w.z;
            a3s += a.w * w.w;
        }
    }
    float v = leaky_((a0 + a1) + (a2s + a3s) + b1[f]);
    out[((size_t)bb * TT + t0 + tl) * FF + f] = v;
}

// ---------------- launch ----------------
extern "C" void kernel_launch(void* const* d_in, const int* in_sizes, int n_in,
                              void* d_out, int out_size) {
    const float* x        = (const float*)d_in[0];
    const float* enc_Wih  = (const float*)d_in[1];
    const float* enc_Whh  = (const float*)d_in[2];
    const float* enc_bih  = (const float*)d_in[3];
    const float* enc_bhh  = (const float*)d_in[4];
    const float* g1_Wih_f = (const float*)d_in[5];
    const float* g1_Whh_f = (const float*)d_in[6];
    const float* g1_bih_f = (const float*)d_in[7];
    const float* g1_bhh_f = (const float*)d_in[8];
    const float* g1_Wih_b = (const float*)d_in[9];
    const float* g1_Whh_b = (const float*)d_in[10];
    const float* g1_bih_b = (const float*)d_in[11];
    const float* g1_bhh_b = (const float*)d_in[12];
    const float* g2_Wih   = (const float*)d_in[13];
    const float* g2_Whh   = (const float*)d_in[14];
    const float* g2_bih   = (const float*)d_in[15];
    const float* g2_bhh   = (const float*)d_in[16];
    const float* w3       = (const float*)d_in[17];
    const float* b3       = (const float*)d_in[18];
    const float* w2       = (const float*)d_in[19];
    const float* b2       = (const float*)d_in[20];
    const float* w1       = (const float*)d_in[21];
    const float* b1       = (const float*)d_in[22];
    float* out = (float*)d_out;

    k_enc_xp<<<(BB * TT * 48 + 255) / 256, 256>>>(x, enc_Wih, enc_bih);
    k_enc_rec<<<32, 128>>>(enc_Whh, enc_bhh);
    k_g1<<<512, 256>>>(g1_Wih_f, g1_Whh_f, g1_bih_f, g1_bhh_f,
                       g1_Wih_b, g1_Whh_b, g1_bih_b, g1_bhh_b);
    {
        dim3 g(BB * TT / 64, FF);
        k_xp2<<<g, 256>>>(g2_Wih, g2_bih);
    }
    k_g2<<<256, 256>>>(g2_Whh, g2_bhh);
    {
        dim3 g(TT / 64, BB, FF);
        k_conv3<<<g, 256>>>(w3, b3);
        k_conv2<<<g, 256>>>(w2, b2);
        k_conv1<<<g, 64>>>(w1, b1, out);
    }
}

// round 2
// speedup vs baseline: 1.4428x; 1.4428x over previous
#include <cuda_runtime.h>
#include <cuda_bf16.h>
#include <math.h>
#include <stdint.h>

#define BB 128
#define TT 512
#define FF 16
#define HH 32

// ---------------- scratch (device globals; no runtime allocation) ----------------
__device__ float d_xpe[BB * TT * 48];
__device__ float d_h  [BB * TT * FF];
__device__ float d_u1 [(size_t)FF * BB * TT * 64];
__device__ float d_xp2[(size_t)FF * BB * TT * 96];
__device__ float d_v2 [(size_t)FF * BB * TT * 32];
__device__ float d_a3 [(size_t)FF * BB * TT * 64];
__device__ float d_a2 [(size_t)FF * BB * TT * 128];

// pre-split bf16 weights for tensor-core convs, layout [f][co][K]
__device__ __nv_bfloat16 d_w3h[16 * 64 * 160];
__device__ __nv_bfloat16 d_w3l[16 * 64 * 160];
__device__ __nv_bfloat16 d_w2h[16 * 128 * 320];
__device__ __nv_bfloat16 d_w2l[16 * 128 * 320];

__device__ __forceinline__ float sigmoidf_(float x) {
    return 1.0f / (1.0f + __expf(-x));
}
__device__ __forceinline__ float tanhf_(float x) {
    float ax = fabsf(x);
    float e  = __expf(-2.0f * ax);
    float t  = (1.0f - e) / (1.0f + e);
    return copysignf(t, x);
}
__device__ __forceinline__ float leaky_(float v) {
    return v >= 0.0f ? v : 0.01f * v;
}

// ---------------- tensor-core helpers ----------------
__device__ __forceinline__ void mma16816(float* c, const uint32_t* a, const uint32_t* b) {
    asm volatile(
        "mma.sync.aligned.m16n8k16.row.col.f32.bf16.bf16.f32 "
        "{%0,%1,%2,%3},{%4,%5,%6,%7},{%8,%9},{%0,%1,%2,%3};"
        : "+f"(c[0]), "+f"(c[1]), "+f"(c[2]), "+f"(c[3])
        : "r"(a[0]), "r"(a[1]), "r"(a[2]), "r"(a[3]), "r"(b[0]), "r"(b[1]));
}
__device__ __forceinline__ uint32_t ld2bf(const __nv_bfloat16* p) {
    return *(const uint32_t*)p;
}
__device__ __forceinline__ void cp16(void* dst, const void* src) {
    uint32_t d = (uint32_t)__cvta_generic_to_shared(dst);
    asm volatile("cp.async.ca.shared.global [%0],[%1],16;" :: "r"(d), "l"(src));
}
#define CP_COMMIT() asm volatile("cp.async.commit_group;")
#define CP_WAIT0()  asm volatile("cp.async.wait_group 0;")
#define CP_WAIT1()  asm volatile("cp.async.wait_group 1;")

__device__ __forceinline__ void split_bf16(float v, __nv_bfloat16& hi, __nv_bfloat16& lo) {
    hi = __float2bfloat16(v);
    lo = __float2bfloat16(v - __bfloat162float(hi));
}

// ---------------- kernel: weight pre-split for conv3/conv2 ----------------
// Wsp3[f][co][kp*32+ci] = w3[f][ci][co][4-kp] ; Wsp2[f][co][kp*64+ci] = w2[f][ci][co][4-kp]
__global__ void k_wprep(const float* __restrict__ w3, const float* __restrict__ w2) {
    int idx = blockIdx.x * blockDim.x + threadIdx.x;
    const int N3 = 16 * 64 * 160;
    const int N2 = 16 * 128 * 320;
    if (idx < N3) {
        int f  = idx / (64 * 160);
        int r  = idx % (64 * 160);
        int co = r / 160;
        int k  = r % 160;
        int kp = k / 32, ci = k % 32;
        float v = w3[((size_t)(f * 32 + ci) * 64 + co) * 5 + (4 - kp)];
        split_bf16(v, d_w3h[idx], d_w3l[idx]);
    } else if (idx < N3 + N2) {
        int j  = idx - N3;
        int f  = j / (128 * 320);
        int r  = j % (128 * 320);
        int co = r / 320;
        int k  = r % 320;
        int kp = k / 64, ci = k % 64;
        float v = w2[((size_t)(f * 64 + ci) * 128 + co) * 5 + (4 - kp)];
        split_bf16(v, d_w2h[j], d_w2l[j]);
    }
}

// ---------------- kernel 0: encoder input projection ----------------
__global__ void k_enc_xp(const float* __restrict__ x,
                         const float* __restrict__ Wih,
                         const float* __restrict__ bih) {
    int idx = blockIdx.x * blockDim.x + threadIdx.x;
    if (idx >= BB * TT * 48) return;
    int g  = idx % 48;
    int bt = idx / 48;
    int b  = bt / TT;
    int t  = bt % TT;
    float x0 = x[b * 2 * TT + t];
    float x1 = x[b * 2 * TT + TT + t];
    d_xpe[idx] = x0 * Wih[g * 2] + x1 * Wih[g * 2 + 1] + bih[g];
}

// ---------------- kernel 1: encoder GRU recurrence (hidden=16) ----------------
__global__ void k_enc_rec(const float* __restrict__ Whh,
                          const float* __restrict__ bhh) {
    int warp = (blockIdx.x * blockDim.x + threadIdx.x) >> 5;
    int l    = threadIdx.x & 31;
    if (warp >= BB) return;
    int b = warp;

    float w0[16], w1[16];
#pragma unroll
    for (int k = 0; k < 16; k++) {
        w0[k] = Whh[l * 16 + k];
        w1[k] = (l < 16) ? Whh[(32 + l) * 16 + k] : 0.0f;
    }
    float bh0 = bhh[l];
    float bh1 = (l < 16) ? bhh[32 + l] : 0.0f;

    float h = 0.0f;
    const float* xp = d_xpe + (size_t)b * TT * 48;
    float* ho = d_h + (size_t)b * TT * FF;

    for (int t = 0; t < TT; t++) {
        float xpa = xp[t * 48 + l];
        float xpn = (l < 16) ? xp[t * 48 + 32 + l] : 0.0f;
        float a0 = bh0, a1 = bh1;
#pragma unroll
        for (int k = 0; k < 16; k++) {
            float hk = __shfl_sync(0xffffffffu, h, k);
            a0 += hk * w0[k];
            a1 += hk * w1[k];
        }
        float g = sigmoidf_(xpa + a0);
        float z = __shfl_sync(0xffffffffu, g, l + 16);
        if (l < 16) {
            float n = tanhf_(xpn + g * a1);
            h = (1.0f - z) * n + z * h;
            ho[t * FF + l] = h;
        }
    }
}

// ---------------- kernel 2: per-feature bidirectional GRU ----------------
__global__ __launch_bounds__(256) void k_g1(
    const float* __restrict__ Wih_f, const float* __restrict__ Whh_f,
    const float* __restrict__ bih_f, const float* __restrict__ bhh_f,
    const float* __restrict__ Wih_b, const float* __restrict__ Whh_b,
    const float* __restrict__ bih_b, const float* __restrict__ bhh_b) {
    int gw = (blockIdx.x * 256 + threadIdx.x) >> 5;
    int l  = threadIdx.x & 31;
    int b   = gw & (BB - 1);
    int f   = (gw >> 7) & (FF - 1);
    int dir = gw >> 11;

    const float* Wih = dir ? Wih_b : Wih_f;
    const float* Whh = dir ? Whh_b : Whh_f;
    const float* bih = dir ? bih_b : bih_f;
    const float* bhh = dir ? bhh_b : bhh_f;

    float wr[32], wz[32], wn[32];
    const float* Wr = Whh + (size_t)(f * 96 + l) * 32;
    const float* Wz = Whh + (size_t)(f * 96 + 32 + l) * 32;
    const float* Wn = Whh + (size_t)(f * 96 + 64 + l) * 32;
#pragma unroll
    for (int k = 0; k < 32; k++) { wr[k] = Wr[k]; wz[k] = Wz[k]; wn[k] = Wn[k]; }

    float wir = Wih[f * 96 + l], wiz = Wih[f * 96 + 32 + l], win = Wih[f * 96 + 64 + l];
    float br  = bih[f * 96 + l], bz  = bih[f * 96 + 32 + l], bn  = bih[f * 96 + 64 + l];
    float cr  = bhh[f * 96 + l], cz  = bhh[f * 96 + 32 + l], cn  = bhh[f * 96 + 64 + l];

    float h = 0.0f;
    const float* hin = d_h + (size_t)b * TT * FF + f;
    float* u = d_u1 + (size_t)(f * BB + b) * TT * 64 + dir * 32 + l;

    for (int s = 0; s < TT; s++) {
        int t = dir ? (TT - 1 - s) : s;
        float xi = hin[(size_t)t * FF];
        float ar = cr, az = cz, an = cn;
#pragma unroll
        for (int k = 0; k < 32; k++) {
            float hk = __shfl_sync(0xffffffffu, h, k);
            ar += hk * wr[k];
            az += hk * wz[k];
            an += hk * wn[k];
        }
        float r = sigmoidf_(xi * wir + br + ar);
        float z = sigmoidf_(xi * wiz + bz + az);
        float n = tanhf_(xi * win + bn + r * an);
        h = (1.0f - z) * n + z * h;
        u[(size_t)t * 64] = h;
    }
}

// ---------------- kernel 3: g2 input projection GEMM ----------------
__global__ __launch_bounds__(256) void k_xp2(const float* __restrict__ Wih2,
                                             const float* __restrict__ bih2) {
    __shared__ float sA[64][65];
    __shared__ float sB[64][97];
    int f  = blockIdx.y;
    int r0 = blockIdx.x * 64;
    int tid = threadIdx.x;

    const float* A  = d_u1 + (size_t)f * BB * TT * 64;
    const float* Wb = Wih2 + (size_t)f * 96 * 64;

    for (int i = tid; i < 64 * 64; i += 256) {
        int rr = i >> 6, kk = i & 63;
        sA[rr][kk] = A[(size_t)(r0 + rr) * 64 + kk];
    }
    for (int i = tid; i < 96 * 64; i += 256) {
        int j = i >> 6, kk = i & 63;
        sB[kk][j] = Wb[i];
    }
    __syncthreads();

    int tj = tid & 15;
    int tr = tid >> 4;
    float acc[4][6];
#pragma unroll
    for (int a = 0; a < 4; a++)
#pragma unroll
        for (int c = 0; c < 6; c++) acc[a][c] = bih2[f * 96 + tj * 6 + c];

    for (int k = 0; k < 64; k++) {
        float av[4], bv[6];
#pragma unroll
        for (int a = 0; a < 4; a++) av[a] = sA[tr * 4 + a][k];
#pragma unroll
        for (int c = 0; c < 6; c++) bv[c] = sB[k][tj * 6 + c];
#pragma unroll
        for (int a = 0; a < 4; a++)
#pragma unroll
            for (int c = 0; c < 6; c++) acc[a][c] += av[a] * bv[c];
    }

    __syncthreads();
    float* so = &sB[0][0];
#pragma unroll
    for (int a = 0; a < 4; a++)
#pragma unroll
        for (int c = 0; c < 6; c++) so[(tr * 4 + a) * 96 + tj * 6 + c] = acc[a][c];
    __syncthreads();
    float* C = d_xp2 + (size_t)f * BB * TT * 96 + (size_t)r0 * 96;
    for (int i = tid; i < 64 * 96; i += 256) C[i] = so[i];
}

// ---------------- kernel 4: g2 GRU recurrence ----------------
__global__ __launch_bounds__(256) void k_g2(const float* __restrict__ Whh2,
                                            const float* __restrict__ bhh2) {
    int gw = (blockIdx.x * 256 + threadIdx.x) >> 5;
    int l  = threadIdx.x & 31;
    int b = gw & (BB - 1);
    int f = gw >> 7;

    float wr[32], wz[32], wn[32];
    const float* Wr = Whh2 + (size_t)(f * 96 + l) * 32;
    const float* Wz = Whh2 + (size_t)(f * 96 + 32 + l) * 32;
    const float* Wn = Whh2 + (size_t)(f * 96 + 64 + l) * 32;
#pragma unroll
    for (int k = 0; k < 32; k++) { wr[k] = Wr[k]; wz[k] = Wz[k]; wn[k] = Wn[k]; }
    float cr = bhh2[f * 96 + l], cz = bhh2[f * 96 + 32 + l], cn = bhh2[f * 96 + 64 + l];

    float h = 0.0f;
    const float* XP = d_xp2 + ((size_t)f * BB + b) * TT * 96;
    float* V = d_v2 + ((size_t)f * BB + b) * TT * 32 + l;

    for (int t = 0; t < TT; t++) {
        const float* xt = XP + (size_t)t * 96;
        float xr = xt[l], xz = xt[32 + l], xn = xt[64 + l];
        float ar = cr, az = cz, an = cn;
#pragma unroll
        for (int k = 0; k < 32; k++) {
            float hk = __shfl_sync(0xffffffffu, h, k);
            ar += hk * wr[k];
            az += hk * wz[k];
            an += hk * wn[k];
        }
        float r = sigmoidf_(xr + ar);
        float z = sigmoidf_(xz + az);
        float n = tanhf_(xn + r * an);
        h = (1.0f - z) * n + z * h;
        V[(size_t)t * 32] = h;
    }
}

// ---------------- kernel 5: convT 32->64, tensor cores, bf16 2-split ----------------
// per block: (f, b, t-tile of 128). C[t][co] = sum_K A[t][K] B[K][co], K = kp*32+ci (160)
// smem elems: sxh[132*40], sxl[132*40], sbh[64*168], sbl[64*168]
__global__ __launch_bounds__(256) void k_conv3_tc(const float* __restrict__ b3) {
    extern __shared__ __nv_bfloat16 sm3[];
    __nv_bfloat16* sxh = sm3;
    __nv_bfloat16* sxl = sm3 + 132 * 40;
    __nv_bfloat16* sbh = sm3 + 2 * 132 * 40;
    __nv_bfloat16* sbl = sbh + 64 * 168;

    int f = blockIdx.z, b = blockIdx.y, t0 = blockIdx.x * 128;
    int tid = threadIdx.x;
    int wid = tid >> 5, l = tid & 31;
    int wt = wid >> 1, wc = wid & 1;   // warp tile: 32 t-rows, 32 co

    // B: cp.async the whole pre-split weight tile [64co][160k]
    for (int i = tid; i < 2560; i += 256) {
        int split = i / 1280;
        int r = i % 1280;
        int co = r / 20, seg = r % 20;
        const __nv_bfloat16* src = (split ? d_w3l : d_w3h) + ((size_t)(f * 64 + co)) * 160 + seg * 8;
        __nv_bfloat16* dst = (split ? sbl : sbh) + co * 168 + seg * 8;
        cp16(dst, src);
    }
    CP_COMMIT();

    // A window: t in [t0-2, t0+129], 132 rows x 32 ci, split into hi/lo
    const float* X = d_v2 + ((size_t)f * BB + b) * TT * 32;
    for (int i = tid; i < 132 * 32; i += 256) {
        int tt = i >> 5, ci = i & 31;
        int t = t0 - 2 + tt;
        float v = (t >= 0 && t < TT) ? X[(size_t)t * 32 + ci] : 0.0f;
        __nv_bfloat16 hi, lo;
        split_bf16(v, hi, lo);
        sxh[tt * 40 + ci] = hi;
        sxl[tt * 40 + ci] = lo;
    }
    CP_WAIT0();
    __syncthreads();

    float acc[2][4][4];
#pragma unroll
    for (int mt = 0; mt < 2; mt++)
#pragma unroll
        for (int nt = 0; nt < 4; nt++)
#pragma unroll
            for (int q = 0; q < 4; q++) acc[mt][nt][q] = 0.0f;

    int q4 = 2 * (l & 3);
    int r4 = l >> 2;

#pragma unroll
    for (int s = 0; s < 10; s++) {
        int kp = s >> 1;
        int col = (s & 1) * 16 + q4;
        uint32_t Ah[2][4], Al[2][4];
#pragma unroll
        for (int mt = 0; mt < 2; mt++) {
            int row = wt * 32 + mt * 16 + r4 + kp;
            const __nv_bfloat16* ph = sxh + row * 40 + col;
            const __nv_bfloat16* pl = sxl + row * 40 + col;
            Ah[mt][0] = ld2bf(ph);            Ah[mt][1] = ld2bf(ph + 8 * 40);
            Ah[mt][2] = ld2bf(ph + 8);        Ah[mt][3] = ld2bf(ph + 8 * 40 + 8);
            Al[mt][0] = ld2bf(pl);            Al[mt][1] = ld2bf(pl + 8 * 40);
            Al[mt][2] = ld2bf(pl + 8);        Al[mt][3] = ld2bf(pl + 8 * 40 + 8);
        }
        int bk = s * 16 + q4;
#pragma unroll
        for (int nt = 0; nt < 4; nt++) {
            int co = wc * 32 + nt * 8 + r4;
            uint32_t Bh[2], Bl[2];
            const __nv_bfloat16* pb = sbh + co * 168 + bk;
            const __nv_bfloat16* pc = sbl + co * 168 + bk;
            Bh[0] = ld2bf(pb); Bh[1] = ld2bf(pb + 8);
            Bl[0] = ld2bf(pc); Bl[1] = ld2bf(pc + 8);
#pragma unroll
            for (int mt = 0; mt < 2; mt++) {
                mma16816(acc[mt][nt], Ah[mt], Bh);
                mma16816(acc[mt][nt], Ah[mt], Bl);
                mma16816(acc[mt][nt], Al[mt], Bh);
            }
        }
    }

    // epilogue: bias + leaky, store fp32
    float* Y = d_a3 + (((size_t)f * BB + b) * TT + t0) * 64;
#pragma unroll
    for (int nt = 0; nt < 4; nt++) {
        int co = wc * 32 + nt * 8 + q4;
        float b0 = b3[f * 64 + co], b1 = b3[f * 64 + co + 1];
#pragma unroll
        for (int mt = 0; mt < 2; mt++) {
            int t = wt * 32 + mt * 16 + r4;
            float2 v0 = make_float2(leaky_(acc[mt][nt][0] + b0), leaky_(acc[mt][nt][1] + b1));
            float2 v1 = make_float2(leaky_(acc[mt][nt][2] + b0), leaky_(acc[mt][nt][3] + b1));
            *(float2*)&Y[(size_t)t * 64 + co] = v0;
            *(float2*)&Y[(size_t)(t + 8) * 64 + co] = v1;
        }
    }
}

// ---------------- kernel 6: convT 64->128, tensor cores, bf16 2-split ----------------
// per block: (f, b, t-tile of 128). K = kp*64+ci (320), streamed in 20 chunks of 16.
// smem elems: sxh[132*72], sxl[132*72], sb[2buf][2split][128*24]
__global__ __launch_bounds__(256) void k_conv2_tc(const float* __restrict__ b2) {
    extern __shared__ __nv_bfloat16 sm2[];
    __nv_bfloat16* sxh = sm2;
    __nv_bfloat16* sxl = sm2 + 132 * 72;
    __nv_bfloat16* sbb = sm2 + 2 * 132 * 72;   // + (buf*2+split)*3072

    int f = blockIdx.z, b = blockIdx.y, t0 = blockIdx.x * 128;
    int tid = threadIdx.x;
    int wid = tid >> 5, l = tid & 31;
    int wt = wid >> 1, wc = wid & 1;   // warp tile: 32 t-rows, 64 co

    int lco = tid >> 1, lhalf = tid & 1;  // B loader mapping: 128co x 2 segs
    const __nv_bfloat16* wsrc_h = d_w2h + ((size_t)f * 128 + lco) * 320 + lhalf * 8;
    const __nv_bfloat16* wsrc_l = d_w2l + ((size_t)f * 128 + lco) * 320 + lhalf * 8;
    __nv_bfloat16* wdst0 = sbb + lco * 24 + lhalf * 8;

    // prefetch B chunk 0 into buf 0
    cp16(wdst0,                wsrc_h);
    cp16(wdst0 + 3072,         wsrc_l);
    CP_COMMIT();

    // A window: 132 rows x 64 ci, hi/lo split
    const float* X = d_a3 + ((size_t)f * BB + b) * TT * 64;
    for (int i = tid; i < 132 * 64; i += 256) {
        int tt = i >> 6, ci = i & 63;
        int t = t0 - 2 + tt;
        float v = (t >= 0 && t < TT) ? X[(size_t)t * 64 + ci] : 0.0f;
        __nv_bfloat16 hi, lo;
        split_bf16(v, hi, lo);
        sxh[tt * 72 + ci] = hi;
        sxl[tt * 72 + ci] = lo;
    }
    __syncthreads();

    float acc[2][8][4];
#pragma unroll
    for (int mt = 0; mt < 2; mt++)
#pragma unroll
        for (int nt = 0; nt < 8; nt++)
#pragma unroll
            for (int q = 0; q < 4; q++) acc[mt][nt][q] = 0.0f;

    int q4 = 2 * (l & 3);
    int r4 = l >> 2;

    for (int s = 0; s < 20; s++) {
        // prefetch next chunk
        if (s + 1 < 20) {
            __nv_bfloat16* wdst = sbb + ((s + 1) & 1) * 6144 + lco * 24 + lhalf * 8;
            cp16(wdst,        wsrc_h + (s + 1) * 16);
            cp16(wdst + 3072, wsrc_l + (s + 1) * 16);
        }
        CP_COMMIT();
        CP_WAIT1();
        __syncthreads();

        const __nv_bfloat16* sbh = sbb + (s & 1) * 6144;
        const __nv_bfloat16* sbl = sbh + 3072;
        int kp = s >> 2;
        int col = (s & 3) * 16 + q4;

        uint32_t Ah[2][4], Al[2][4];
#pragma unroll
        for (int mt = 0; mt < 2; mt++) {
            int row = wt * 32 + mt * 16 + r4 + kp;
            const __nv_bfloat16* ph = sxh + row * 72 + col;
            const __nv_bfloat16* pl = sxl + row * 72 + col;
            Ah[mt][0] = ld2bf(ph);            Ah[mt][1] = ld2bf(ph + 8 * 72);
            Ah[mt][2] = ld2bf(ph + 8);        Ah[mt][3] = ld2bf(ph + 8 * 72 + 8);
            Al[mt][0] = ld2bf(pl);            Al[mt][1] = ld2bf(pl + 8 * 72);
            Al[mt][2] = ld2bf(pl + 8);        Al[mt][3] = ld2bf(pl + 8 * 72 + 8);
        }
#pragma unroll
        for (int nt = 0; nt < 8; nt++) {
            int co = wc * 64 + nt * 8 + r4;
            uint32_t Bh[2], Bl[2];
            const __nv_bfloat16* pb = sbh + co * 24 + q4;
            const __nv_bfloat16* pc = sbl + co * 24 + q4;
            Bh[0] = ld2bf(pb); Bh[1] = ld2bf(pb + 8);
            Bl[0] = ld2bf(pc); Bl[1] = ld2bf(pc + 8);
#pragma unroll
            for (int mt = 0; mt < 2; mt++) {
                mma16816(acc[mt][nt], Ah[mt], Bh);
                mma16816(acc[mt][nt], Ah[mt], Bl);
                mma16816(acc[mt][nt], Al[mt], Bh);
            }
        }
        __syncthreads();
    }

    // epilogue: bias + leaky, store fp32
    float* Y = d_a2 + (((size_t)f * BB + b) * TT + t0) * 128;
#pragma unroll
    for (int nt = 0; nt < 8; nt++) {
        int co = wc * 64 + nt * 8 + q4;
        float b0 = b2[f * 128 + co], b1 = b2[f * 128 + co + 1];
#pragma unroll
        for (int mt = 0; mt < 2; mt++) {
            int t = wt * 32 + mt * 16 + r4;
            float2 v0 = make_float2(leaky_(acc[mt][nt][0] + b0), leaky_(acc[mt][nt][1] + b1));
            float2 v1 = make_float2(leaky_(acc[mt][nt][2] + b0), leaky_(acc[mt][nt][3] + b1));
            *(float2*)&Y[(size_t)t * 128 + co] = v0;
            *(float2*)&Y[(size_t)(t + 8) * 128 + co] = v1;
        }
    }
}

// ---------------- kernel 7: convT 128 -> 1 + leaky, write final output ----------------
__global__ __launch_bounds__(64) void k_conv1(const float* __restrict__ w1,
                                              const float* __restrict__ b1,
                                              float* __restrict__ out) {
    __shared__ float sx[68][132];
    __shared__ float sw[5][128];
    int f = blockIdx.z, bb = blockIdx.y, t0 = blockIdx.x * 64;
    int tid = threadIdx.x;

    const float* X = d_a2 + ((size_t)f * BB + bb) * TT * 128;
    for (int i = tid; i < 68 * 128; i += 64) {
        int tt = i >> 7, ci = i & 127;
        int t = t0 - 2 + tt;
        sx[tt][ci] = (t >= 0 && t < TT) ? X[(size_t)t * 128 + ci] : 0.0f;
    }
    for (int i = tid; i < 5 * 128; i += 64) {
        int j = i >> 7, ci = i & 127;
        sw[j][ci] = w1[f * 640 + ci * 5 + (4 - j)];
    }
    __syncthreads();

    int tl = tid;
    float a0 = 0.0f, a1 = 0.0f, a2s = 0.0f, a3s = 0.0f;
#pragma unroll
    for (int j = 0; j < 5; j++) {
        const float* xr = &sx[tl + j][0];
        const float* wr_ = &sw[j][0];
#pragma unroll
        for (int ci = 0; ci < 128; ci += 4) {
            float4 a = *(const float4*)&xr[ci];
            float4 w = *(const float4*)&wr_[ci];
            a0 += a.x * w.x;
            a1 += a.y * w.y;
            a2s += a.z * w.z;
            a3s += a.w * w.w;
        }
    }
    float v = leaky_((a0 + a1) + (a2s + a3s) + b1[f]);
    out[((size_t)bb * TT + t0 + tl) * FF + f] = v;
}

// ---------------- launch ----------------
extern "C" void kernel_launch(void* const* d_in, const int* in_sizes, int n_in,
                              void* d_out, int out_size) {
    const float* x        = (const float*)d_in[0];
    const float* enc_Wih  = (const float*)d_in[1];
    const float* enc_Whh  = (const float*)d_in[2];
    const float* enc_bih  = (const float*)d_in[3];
    const float* enc_bhh  = (const float*)d_in[4];
    const float* g1_Wih_f = (const float*)d_in[5];
    const float* g1_Whh_f = (const float*)d_in[6];
    const float* g1_bih_f = (const float*)d_in[7];
    const float* g1_bhh_f = (const float*)d_in[8];
    const float* g1_Wih_b = (const float*)d_in[9];
    const float* g1_Whh_b = (const float*)d_in[10];
    const float* g1_bih_b = (const float*)d_in[11];
    const float* g1_bhh_b = (const float*)d_in[12];
    const float* g2_Wih   = (const float*)d_in[13];
    const float* g2_Whh   = (const float*)d_in[14];
    const float* g2_bih   = (const float*)d_in[15];
    const float* g2_bhh   = (const float*)d_in[16];
    const float* w3       = (const float*)d_in[17];
    const float* b3       = (const float*)d_in[18];
    const float* w2       = (const float*)d_in[19];
    const float* b2       = (const float*)d_in[20];
    const float* w1       = (const float*)d_in[21];
    const float* b1       = (const float*)d_in[22];
    float* out = (float*)d_out;

    const int SMEM3 = (2 * 132 * 40 + 2 * 64 * 168) * 2;   // 64128 B
    const int SMEM2 = (2 * 132 * 72 + 4 * 128 * 24) * 2;   // 62592 B
    static bool attr_set = false;
    if (!attr_set) {
        cudaFuncSetAttribute(k_conv3_tc, cudaFuncAttributeMaxDynamicSharedMemorySize, SMEM3);
        cudaFuncSetAttribute(k_conv2_tc, cudaFuncAttributeMaxDynamicSharedMemorySize, SMEM2);
        attr_set = true;
    }

    k_wprep<<<(16 * 64 * 160 + 16 * 128 * 320 + 255) / 256, 256>>>(w3, w2);
    k_enc_xp<<<(BB * TT * 48 + 255) / 256, 256>>>(x, enc_Wih, enc_bih);
    k_enc_rec<<<32, 128>>>(enc_Whh, enc_bhh);
    k_g1<<<512, 256>>>(g1_Wih_f, g1_Whh_f, g1_bih_f, g1_bhh_f,
                       g1_Wih_b, g1_Whh_b, g1_bih_b, g1_bhh_b);
    {
        dim3 g(BB * TT / 64, FF);
        k_xp2<<<g, 256>>>(g2_Wih, g2_bih);
    }
    k_g2<<<256, 256>>>(g2_Whh, g2_bhh);
    {
        dim3 g(TT / 128, BB, FF);
        k_conv3_tc<<<g, 256, SMEM3>>>(b3);
        k_conv2_tc<<<g, 256, SMEM2>>>(b2);
    }
    {
        dim3 g(TT / 64, BB, FF);
        k_conv1<<<g, 64>>>(w1, b1, out);
    }
}

// round 3
// speedup vs baseline: 1.5435x; 1.0698x over previous
#include <cuda_runtime.h>
#include <cuda_bf16.h>
#include <math.h>
#include <stdint.h>

#define BB 128
#define TT 512
#define FF 16
#define HH 32

// ---------------- scratch (device globals; no runtime allocation) ----------------
__device__ float d_xpe[BB * TT * 48];
__device__ float d_h  [BB * TT * FF];
__device__ float d_u1 [(size_t)FF * BB * TT * 64];
__device__ float d_xp2[(size_t)FF * BB * TT * 96];
__device__ float d_v2 [(size_t)FF * BB * TT * 32];
__device__ float d_a3 [(size_t)FF * BB * TT * 64];
__device__ float d_a2 [(size_t)FF * BB * TT * 128];

// pre-split bf16 weights for tensor-core convs, layout [f][co][K]
__device__ __nv_bfloat16 d_w3h[16 * 64 * 160];
__device__ __nv_bfloat16 d_w3l[16 * 64 * 160];
__device__ __nv_bfloat16 d_w2h[16 * 128 * 320];
__device__ __nv_bfloat16 d_w2l[16 * 128 * 320];

__device__ __forceinline__ float sigmoidf_(float x) {
    return 1.0f / (1.0f + __expf(-x));
}
__device__ __forceinline__ float tanhf_(float x) {
    float ax = fabsf(x);
    float e  = __expf(-2.0f * ax);
    float t  = (1.0f - e) / (1.0f + e);
    return copysignf(t, x);
}
__device__ __forceinline__ float leaky_(float v) {
    return v >= 0.0f ? v : 0.01f * v;
}

// ---------------- tensor-core helpers ----------------
__device__ __forceinline__ void mma16816(float* c, const uint32_t* a, const uint32_t* b) {
    asm volatile(
        "mma.sync.aligned.m16n8k16.row.col.f32.bf16.bf16.f32 "
        "{%0,%1,%2,%3},{%4,%5,%6,%7},{%8,%9},{%0,%1,%2,%3};"
        : "+f"(c[0]), "+f"(c[1]), "+f"(c[2]), "+f"(c[3])
        : "r"(a[0]), "r"(a[1]), "r"(a[2]), "r"(a[3]), "r"(b[0]), "r"(b[1]));
}
__device__ __forceinline__ uint32_t ld2bf(const __nv_bfloat16* p) {
    return *(const uint32_t*)p;
}
__device__ __forceinline__ void cp16(void* dst, const void* src) {
    uint32_t d = (uint32_t)__cvta_generic_to_shared(dst);
    asm volatile("cp.async.ca.shared.global [%0],[%1],16;" :: "r"(d), "l"(src));
}
#define CP_COMMIT() asm volatile("cp.async.commit_group;")
#define CP_WAIT0()  asm volatile("cp.async.wait_group 0;")
#define CP_WAIT1()  asm volatile("cp.async.wait_group 1;")

__device__ __forceinline__ void split_bf16(float v, __nv_bfloat16& hi, __nv_bfloat16& lo) {
    hi = __float2bfloat16(v);
    lo = __float2bfloat16(v - __bfloat162float(hi));
}

// ---------------- kernel: weight pre-split for conv3/conv2 ----------------
__global__ void k_wprep(const float* __restrict__ w3, const float* __restrict__ w2) {
    int idx = blockIdx.x * blockDim.x + threadIdx.x;
    const int N3 = 16 * 64 * 160;
    const int N2 = 16 * 128 * 320;
    if (idx < N3) {
        int f  = idx / (64 * 160);
        int r  = idx % (64 * 160);
        int co = r / 160;
        int k  = r % 160;
        int kp = k / 32, ci = k % 32;
        float v = w3[((size_t)(f * 32 + ci) * 64 + co) * 5 + (4 - kp)];
        split_bf16(v, d_w3h[idx], d_w3l[idx]);
    } else if (idx < N3 + N2) {
        int j  = idx - N3;
        int f  = j / (128 * 320);
        int r  = j % (128 * 320);
        int co = r / 320;
        int k  = r % 320;
        int kp = k / 64, ci = k % 64;
        float v = w2[((size_t)(f * 64 + ci) * 128 + co) * 5 + (4 - kp)];
        split_bf16(v, d_w2h[j], d_w2l[j]);
    }
}

// ---------------- kernel 0: encoder input projection ----------------
__global__ void k_enc_xp(const float* __restrict__ x,
                         const float* __restrict__ Wih,
                         const float* __restrict__ bih) {
    int idx = blockIdx.x * blockDim.x + threadIdx.x;
    if (idx >= BB * TT * 48) return;
    int g  = idx % 48;
    int bt = idx / 48;
    int b  = bt / TT;
    int t  = bt % TT;
    float x0 = x[b * 2 * TT + t];
    float x1 = x[b * 2 * TT + TT + t];
    d_xpe[idx] = x0 * Wih[g * 2] + x1 * Wih[g * 2 + 1] + bih[g];
}

// ---------------- kernel 1: encoder GRU recurrence (hidden=16) ----------------
__global__ void k_enc_rec(const float* __restrict__ Whh,
                          const float* __restrict__ bhh) {
    int warp = (blockIdx.x * blockDim.x + threadIdx.x) >> 5;
    int l    = threadIdx.x & 31;
    if (warp >= BB) return;
    int b = warp;

    float w0[16], w1[16];
#pragma unroll
    for (int k = 0; k < 16; k++) {
        w0[k] = Whh[l * 16 + k];
        w1[k] = (l < 16) ? Whh[(32 + l) * 16 + k] : 0.0f;
    }
    float bh0 = bhh[l];
    float bh1 = (l < 16) ? bhh[32 + l] : 0.0f;

    float h = 0.0f;
    const float* xp = d_xpe + (size_t)b * TT * 48;
    float* ho = d_h + (size_t)b * TT * FF;

    for (int t = 0; t < TT; t++) {
        float xpa = xp[t * 48 + l];
        float xpn = (l < 16) ? xp[t * 48 + 32 + l] : 0.0f;
        float a0 = bh0, a1 = bh1;
#pragma unroll
        for (int k = 0; k < 16; k++) {
            float hk = __shfl_sync(0xffffffffu, h, k);
            a0 += hk * w0[k];
            a1 += hk * w1[k];
        }
        float g = sigmoidf_(xpa + a0);
        float z = __shfl_sync(0xffffffffu, g, l + 16);
        if (l < 16) {
            float n = tanhf_(xpn + g * a1);
            h = (1.0f - z) * n + z * h;
            ho[t * FF + l] = h;
        }
    }
}

// ---------------- kernel 2: per-feature bidirectional GRU ----------------
// 2048 warps (256 blocks); each warp serially runs 2 sequences -> single wave.
__global__ __launch_bounds__(256, 2) void k_g1(
    const float* __restrict__ Wih_f, const float* __restrict__ Whh_f,
    const float* __restrict__ bih_f, const float* __restrict__ bhh_f,
    const float* __restrict__ Wih_b, const float* __restrict__ Whh_b,
    const float* __restrict__ bih_b, const float* __restrict__ bhh_b) {
    int gw0 = (blockIdx.x * 256 + threadIdx.x) >> 5;   // 0..2047
    int l   = threadIdx.x & 31;

    for (int rep = 0; rep < 2; rep++) {
        int gw  = gw0 + rep * 2048;                    // 0..4095
        int b   = gw & (BB - 1);
        int f   = (gw >> 7) & (FF - 1);
        int dir = gw >> 11;

        const float* Wih = dir ? Wih_b : Wih_f;
        const float* Whh = dir ? Whh_b : Whh_f;
        const float* bih = dir ? bih_b : bih_f;
        const float* bhh = dir ? bhh_b : bhh_f;

        float wr[32], wz[32], wn[32];
        const float* Wr = Whh + (size_t)(f * 96 + l) * 32;
        const float* Wz = Whh + (size_t)(f * 96 + 32 + l) * 32;
        const float* Wn = Whh + (size_t)(f * 96 + 64 + l) * 32;
#pragma unroll
        for (int k = 0; k < 32; k++) { wr[k] = Wr[k]; wz[k] = Wz[k]; wn[k] = Wn[k]; }

        float wir = Wih[f * 96 + l], wiz = Wih[f * 96 + 32 + l], win = Wih[f * 96 + 64 + l];
        float br  = bih[f * 96 + l], bz  = bih[f * 96 + 32 + l], bn  = bih[f * 96 + 64 + l];
        float cr  = bhh[f * 96 + l], cz  = bhh[f * 96 + 32 + l], cn  = bhh[f * 96 + 64 + l];

        float h = 0.0f;
        const float* hin = d_h + (size_t)b * TT * FF + f;
        float* u = d_u1 + (size_t)(f * BB + b) * TT * 64 + dir * 32 + l;

        for (int s = 0; s < TT; s++) {
            int t = dir ? (TT - 1 - s) : s;
            float xi = hin[(size_t)t * FF];
            float ar = cr, az = cz, an = cn;
#pragma unroll
            for (int k = 0; k < 32; k++) {
                float hk = __shfl_sync(0xffffffffu, h, k);
                ar += hk * wr[k];
                az += hk * wz[k];
                an += hk * wn[k];
            }
            float r = sigmoidf_(xi * wir + br + ar);
            float z = sigmoidf_(xi * wiz + bz + az);
            float n = tanhf_(xi * win + bn + r * an);
            h = (1.0f - z) * n + z * h;
            u[(size_t)t * 64] = h;
        }
    }
}

// ---------------- kernel 3: g2 input projection, tensor cores ----------------
// per block: 128 rows x 96 cols, K=64. C = u1 @ Wih2^T + bih2
// smem: sAh/sAl [128][72], sBh/sBl [96][72] bf16
__global__ __launch_bounds__(256) void k_xp2_tc(const float* __restrict__ Wih2,
                                                const float* __restrict__ bih2) {
    extern __shared__ __nv_bfloat16 smx[];
    __nv_bfloat16* sAh = smx;
    __nv_bfloat16* sAl = smx + 128 * 72;
    __nv_bfloat16* sBh = smx + 2 * 128 * 72;
    __nv_bfloat16* sBl = sBh + 96 * 72;

    int f  = blockIdx.y;
    int r0 = blockIdx.x * 128;
    int tid = threadIdx.x;
    int wid = tid >> 5, l = tid & 31;
    int wt = wid >> 1, wc = wid & 1;   // warp tile: 32 rows x 48 cols

    const float* A  = d_u1 + (size_t)f * BB * TT * 64 + (size_t)r0 * 64;
    const float* Wb = Wih2 + (size_t)f * 96 * 64;

    // load + split A (128x64) via float4
    for (int i = tid; i < 128 * 16; i += 256) {
        int rr = i >> 4, kq = i & 15;
        float4 v = *(const float4*)&A[(size_t)rr * 64 + kq * 4];
        __nv_bfloat16 h0, l0, h1, l1, h2, l2, h3, l3;
        split_bf16(v.x, h0, l0); split_bf16(v.y, h1, l1);
        split_bf16(v.z, h2, l2); split_bf16(v.w, h3, l3);
        __nv_bfloat16* ph = sAh + rr * 72 + kq * 4;
        __nv_bfloat16* pl = sAl + rr * 72 + kq * 4;
        ph[0] = h0; ph[1] = h1; ph[2] = h2; ph[3] = h3;
        pl[0] = l0; pl[1] = l1; pl[2] = l2; pl[3] = l3;
    }
    // load + split B (96x64)
    for (int i = tid; i < 96 * 16; i += 256) {
        int j = i >> 4, kq = i & 15;
        float4 v = *(const float4*)&Wb[(size_t)j * 64 + kq * 4];
        __nv_bfloat16 h0, l0, h1, l1, h2, l2, h3, l3;
        split_bf16(v.x, h0, l0); split_bf16(v.y, h1, l1);
        split_bf16(v.z, h2, l2); split_bf16(v.w, h3, l3);
        __nv_bfloat16* ph = sBh + j * 72 + kq * 4;
        __nv_bfloat16* pl = sBl + j * 72 + kq * 4;
        ph[0] = h0; ph[1] = h1; ph[2] = h2; ph[3] = h3;
        pl[0] = l0; pl[1] = l1; pl[2] = l2; pl[3] = l3;
    }
    __syncthreads();

    float acc[2][6][4];
#pragma unroll
    for (int mt = 0; mt < 2; mt++)
#pragma unroll
        for (int nt = 0; nt < 6; nt++)
#pragma unroll
            for (int q = 0; q < 4; q++) acc[mt][nt][q] = 0.0f;

    int q4 = 2 * (l & 3);
    int r4 = l >> 2;

#pragma unroll
    for (int kt = 0; kt < 4; kt++) {
        int col = kt * 16 + q4;
        uint32_t Ah[2][4], Al[2][4];
#pragma unroll
        for (int mt = 0; mt < 2; mt++) {
            int row = wt * 32 + mt * 16 + r4;
            const __nv_bfloat16* ph = sAh + row * 72 + col;
            const __nv_bfloat16* pl = sAl + row * 72 + col;
            Ah[mt][0] = ld2bf(ph);       Ah[mt][1] = ld2bf(ph + 8 * 72);
            Ah[mt][2] = ld2bf(ph + 8);   Ah[mt][3] = ld2bf(ph + 8 * 72 + 8);
            Al[mt][0] = ld2bf(pl);       Al[mt][1] = ld2bf(pl + 8 * 72);
            Al[mt][2] = ld2bf(pl + 8);   Al[mt][3] = ld2bf(pl + 8 * 72 + 8);
        }
#pragma unroll
        for (int nt = 0; nt < 6; nt++) {
            int co = wc * 48 + nt * 8 + r4;
            uint32_t Bh[2], Bl[2];
            const __nv_bfloat16* pb = sBh + co * 72 + col;
            const __nv_bfloat16* pc = sBl + co * 72 + col;
            Bh[0] = ld2bf(pb); Bh[1] = ld2bf(pb + 8);
            Bl[0] = ld2bf(pc); Bl[1] = ld2bf(pc + 8);
#pragma unroll
            for (int mt = 0; mt < 2; mt++) {
                mma16816(acc[mt][nt], Ah[mt], Bh);
                mma16816(acc[mt][nt], Ah[mt], Bl);
                mma16816(acc[mt][nt], Al[mt], Bh);
            }
        }
    }

    float* C = d_xp2 + (size_t)f * BB * TT * 96 + (size_t)r0 * 96;
#pragma unroll
    for (int nt = 0; nt < 6; nt++) {
        int co = wc * 48 + nt * 8 + q4;
        float b0 = bih2[f * 96 + co], b1 = bih2[f * 96 + co + 1];
#pragma unroll
        for (int mt = 0; mt < 2; mt++) {
            int r = wt * 32 + mt * 16 + r4;
            float2 v0 = make_float2(acc[mt][nt][0] + b0, acc[mt][nt][1] + b1);
            float2 v1 = make_float2(acc[mt][nt][2] + b0, acc[mt][nt][3] + b1);
            *(float2*)&C[(size_t)r * 96 + co] = v0;
            *(float2*)&C[(size_t)(r + 8) * 96 + co] = v1;
        }
    }
}

// ---------------- kernel 4: g2 GRU recurrence ----------------
__global__ __launch_bounds__(256, 2) void k_g2(const float* __restrict__ Whh2,
                                               const float* __restrict__ bhh2) {
    int gw = (blockIdx.x * 256 + threadIdx.x) >> 5;
    int l  = threadIdx.x & 31;
    int b = gw & (BB - 1);
    int f = gw >> 7;

    float wr[32], wz[32], wn[32];
    const float* Wr = Whh2 + (size_t)(f * 96 + l) * 32;
    const float* Wz = Whh2 + (size_t)(f * 96 + 32 + l) * 32;
    const float* Wn = Whh2 + (size_t)(f * 96 + 64 + l) * 32;
#pragma unroll
    for (int k = 0; k < 32; k++) { wr[k] = Wr[k]; wz[k] = Wz[k]; wn[k] = Wn[k]; }
    float cr = bhh2[f * 96 + l], cz = bhh2[f * 96 + 32 + l], cn = bhh2[f * 96 + 64 + l];

    float h = 0.0f;
    const float* XP = d_xp2 + ((size_t)f * BB + b) * TT * 96;
    float* V = d_v2 + ((size_t)f * BB + b) * TT * 32 + l;

    for (int t = 0; t < TT; t++) {
        const float* xt = XP + (size_t)t * 96;
        float xr = xt[l], xz = xt[32 + l], xn = xt[64 + l];
        float ar = cr, az = cz, an = cn;
#pragma unroll
        for (int k = 0; k < 32; k++) {
            float hk = __shfl_sync(0xffffffffu, h, k);
            ar += hk * wr[k];
            az += hk * wz[k];
            an += hk * wn[k];
        }
        float r = sigmoidf_(xr + ar);
        float z = sigmoidf_(xz + az);
        float n = tanhf_(xn + r * an);
        h = (1.0f - z) * n + z * h;
        V[(size_t)t * 32] = h;
    }
}

// ---------------- kernel 5: convT 32->64, tensor cores, bf16 2-split ----------------
__global__ __launch_bounds__(256) void k_conv3_tc(const float* __restrict__ b3) {
    extern __shared__ __nv_bfloat16 sm3[];
    __nv_bfloat16* sxh = sm3;
    __nv_bfloat16* sxl = sm3 + 132 * 40;
    __nv_bfloat16* sbh = sm3 + 2 * 132 * 40;
    __nv_bfloat16* sbl = sbh + 64 * 168;

    int f = blockIdx.z, b = blockIdx.y, t0 = blockIdx.x * 128;
    int tid = threadIdx.x;
    int wid = tid >> 5, l = tid & 31;
    int wt = wid >> 1, wc = wid & 1;

    for (int i = tid; i < 2560; i += 256) {
        int split = i / 1280;
        int r = i % 1280;
        int co = r / 20, seg = r % 20;
        const __nv_bfloat16* src = (split ? d_w3l : d_w3h) + ((size_t)(f * 64 + co)) * 160 + seg * 8;
        __nv_bfloat16* dst = (split ? sbl : sbh) + co * 168 + seg * 8;
        cp16(dst, src);
    }
    CP_COMMIT();

    const float* X = d_v2 + ((size_t)f * BB + b) * TT * 32;
    for (int i = tid; i < 132 * 32; i += 256) {
        int tt = i >> 5, ci = i & 31;
        int t = t0 - 2 + tt;
        float v = (t >= 0 && t < TT) ? X[(size_t)t * 32 + ci] : 0.0f;
        __nv_bfloat16 hi, lo;
        split_bf16(v, hi, lo);
        sxh[tt * 40 + ci] = hi;
        sxl[tt * 40 + ci] = lo;
    }
    CP_WAIT0();
    __syncthreads();

    float acc[2][4][4];
#pragma unroll
    for (int mt = 0; mt < 2; mt++)
#pragma unroll
        for (int nt = 0; nt < 4; nt++)
#pragma unroll
            for (int q = 0; q < 4; q++) acc[mt][nt][q] = 0.0f;

    int q4 = 2 * (l & 3);
    int r4 = l >> 2;

#pragma unroll
    for (int s = 0; s < 10; s++) {
        int kp = s >> 1;
        int col = (s & 1) * 16 + q4;
        uint32_t Ah[2][4], Al[2][4];
#pragma unroll
        for (int mt = 0; mt < 2; mt++) {
            int row = wt * 32 + mt * 16 + r4 + kp;
            const __nv_bfloat16* ph = sxh + row * 40 + col;
            const __nv_bfloat16* pl = sxl + row * 40 + col;
            Ah[mt][0] = ld2bf(ph);            Ah[mt][1] = ld2bf(ph + 8 * 40);
            Ah[mt][2] = ld2bf(ph + 8);        Ah[mt][3] = ld2bf(ph + 8 * 40 + 8);
            Al[mt][0] = ld2bf(pl);            Al[mt][1] = ld2bf(pl + 8 * 40);
            Al[mt][2] = ld2bf(pl + 8);        Al[mt][3] = ld2bf(pl + 8 * 40 + 8);
        }
        int bk = s * 16 + q4;
#pragma unroll
        for (int nt = 0; nt < 4; nt++) {
            int co = wc * 32 + nt * 8 + r4;
            uint32_t Bh[2], Bl[2];
            const __nv_bfloat16* pb = sbh + co * 168 + bk;
            const __nv_bfloat16* pc = sbl + co * 168 + bk;
            Bh[0] = ld2bf(pb); Bh[1] = ld2bf(pb + 8);
            Bl[0] = ld2bf(pc); Bl[1] = ld2bf(pc + 8);
#pragma unroll
            for (int mt = 0; mt < 2; mt++) {
                mma16816(acc[mt][nt], Ah[mt], Bh);
                mma16816(acc[mt][nt], Ah[mt], Bl);
                mma16816(acc[mt][nt], Al[mt], Bh);
            }
        }
    }

    float* Y = d_a3 + (((size_t)f * BB + b) * TT + t0) * 64;
#pragma unroll
    for (int nt = 0; nt < 4; nt++) {
        int co = wc * 32 + nt * 8 + q4;
        float b0 = b3[f * 64 + co], b1 = b3[f * 64 + co + 1];
#pragma unroll
        for (int mt = 0; mt < 2; mt++) {
            int t = wt * 32 + mt * 16 + r4;
            float2 v0 = make_float2(leaky_(acc[mt][nt][0] + b0), leaky_(acc[mt][nt][1] + b1));
            float2 v1 = make_float2(leaky_(acc[mt][nt][2] + b0), leaky_(acc[mt][nt][3] + b1));
            *(float2*)&Y[(size_t)t * 64 + co] = v0;
            *(float2*)&Y[(size_t)(t + 8) * 64 + co] = v1;
        }
    }
}

// ---------------- kernel 6: convT 64->128, tensor cores, bf16 2-split ----------------
__global__ __launch_bounds__(256) void k_conv2_tc(const float* __restrict__ b2) {
    extern __shared__ __nv_bfloat16 sm2[];
    __nv_bfloat16* sxh = sm2;
    __nv_bfloat16* sxl = sm2 + 132 * 72;
    __nv_bfloat16* sbb = sm2 + 2 * 132 * 72;

    int f = blockIdx.z, b = blockIdx.y, t0 = blockIdx.x * 128;
    int tid = threadIdx.x;
    int wid = tid >> 5, l = tid & 31;
    int wt = wid >> 1, wc = wid & 1;

    int lco = tid >> 1, lhalf = tid & 1;
    const __nv_bfloat16* wsrc_h = d_w2h + ((size_t)f * 128 + lco) * 320 + lhalf * 8;
    const __nv_bfloat16* wsrc_l = d_w2l + ((size_t)f * 128 + lco) * 320 + lhalf * 8;
    __nv_bfloat16* wdst0 = sbb + lco * 24 + lhalf * 8;

    cp16(wdst0,        wsrc_h);
    cp16(wdst0 + 3072, wsrc_l);
    CP_COMMIT();

    const float* X = d_a3 + ((size_t)f * BB + b) * TT * 64;
    for (int i = tid; i < 132 * 64; i += 256) {
        int tt = i >> 6, ci = i & 63;
        int t = t0 - 2 + tt;
        float v = (t >= 0 && t < TT) ? X[(size_t)t * 64 + ci] : 0.0f;
        __nv_bfloat16 hi, lo;
        split_bf16(v, hi, lo);
        sxh[tt * 72 + ci] = hi;
        sxl[tt * 72 + ci] = lo;
    }
    __syncthreads();

    float acc[2][8][4];
#pragma unroll
    for (int mt = 0; mt < 2; mt++)
#pragma unroll
        for (int nt = 0; nt < 8; nt++)
#pragma unroll
            for (int q = 0; q < 4; q++) acc[mt][nt][q] = 0.0f;

    int q4 = 2 * (l & 3);
    int r4 = l >> 2;

    for (int s = 0; s < 20; s++) {
        if (s + 1 < 20) {
            __nv_bfloat16* wdst = sbb + ((s + 1) & 1) * 6144 + lco * 24 + lhalf * 8;
            cp16(wdst,        wsrc_h + (s + 1) * 16);
            cp16(wdst + 3072, wsrc_l + (s + 1) * 16);
        }
        CP_COMMIT();
        CP_WAIT1();
        __syncthreads();

        const __nv_bfloat16* sbh = sbb + (s & 1) * 6144;
        const __nv_bfloat16* sbl = sbh + 3072;
        int kp = s >> 2;
        int col = (s & 3) * 16 + q4;

        uint32_t Ah[2][4], Al[2][4];
#pragma unroll
        for (int mt = 0; mt < 2; mt++) {
            int row = wt * 32 + mt * 16 + r4 + kp;
            const __nv_bfloat16* ph = sxh + row * 72 + col;
            const __nv_bfloat16* pl = sxl + row * 72 + col;
            Ah[mt][0] = ld2bf(ph);            Ah[mt][1] = ld2bf(ph + 8 * 72);
            Ah[mt][2] = ld2bf(ph + 8);        Ah[mt][3] = ld2bf(ph + 8 * 72 + 8);
            Al[mt][0] = ld2bf(pl);            Al[mt][1] = ld2bf(pl + 8 * 72);
            Al[mt][2] = ld2bf(pl + 8);        Al[mt][3] = ld2bf(pl + 8 * 72 + 8);
        }
#pragma unroll
        for (int nt = 0; nt < 8; nt++) {
            int co = wc * 64 + nt * 8 + r4;
            uint32_t Bh[2], Bl[2];
            const __nv_bfloat16* pb = sbh + co * 24 + q4;
            const __nv_bfloat16* pc = sbl + co * 24 + q4;
            Bh[0] = ld2bf(pb); Bh[1] = ld2bf(pb + 8);
            Bl[0] = ld2bf(pc); Bl[1] = ld2bf(pc + 8);
#pragma unroll
            for (int mt = 0; mt < 2; mt++) {
                mma16816(acc[mt][nt], Ah[mt], Bh);
                mma16816(acc[mt][nt], Ah[mt], Bl);
                mma16816(acc[mt][nt], Al[mt], Bh);
            }
        }
        __syncthreads();
    }

    float* Y = d_a2 + (((size_t)f * BB + b) * TT + t0) * 128;
#pragma unroll
    for (int nt = 0; nt < 8; nt++) {
        int co = wc * 64 + nt * 8 + q4;
        float b0 = b2[f * 128 + co], b1 = b2[f * 128 + co + 1];
#pragma unroll
        for (int mt = 0; mt < 2; mt++) {
            int t = wt * 32 + mt * 16 + r4;
            float2 v0 = make_float2(leaky_(acc[mt][nt][0] + b0), leaky_(acc[mt][nt][1] + b1));
            float2 v1 = make_float2(leaky_(acc[mt][nt][2] + b0), leaky_(acc[mt][nt][3] + b1));
            *(float2*)&Y[(size_t)t * 128 + co] = v0;
            *(float2*)&Y[(size_t)(t + 8) * 128 + co] = v1;
        }
    }
}

// ---------------- kernel 7: convT 128 -> 1 + leaky, write final output ----------------
__global__ __launch_bounds__(64) void k_conv1(const float* __restrict__ w1,
                                              const float* __restrict__ b1,
                                              float* __restrict__ out) {
    __shared__ float sx[68][132];
    __shared__ float sw[5][128];
    int f = blockIdx.z, bb = blockIdx.y, t0 = blockIdx.x * 64;
    int tid = threadIdx.x;

    const float* X = d_a2 + ((size_t)f * BB + bb) * TT * 128;
    for (int i = tid; i < 68 * 128; i += 64) {
        int tt = i >> 7, ci = i & 127;
        int t = t0 - 2 + tt;
        sx[tt][ci] = (t >= 0 && t < TT) ? X[(size_t)t * 128 + ci] : 0.0f;
    }
    for (int i = tid; i < 5 * 128; i += 64) {
        int j = i >> 7, ci = i & 127;
        sw[j][ci] = w1[f * 640 + ci * 5 + (4 - j)];
    }
    __syncthreads();

    int tl = tid;
    float a0 = 0.0f, a1 = 0.0f, a2s = 0.0f, a3s = 0.0f;
#pragma unroll
    for (int j = 0; j < 5; j++) {
        const float* xr = &sx[tl + j][0];
        const float* wr_ = &sw[j][0];
#pragma unroll
        for (int ci = 0; ci < 128; ci += 4) {
            float4 a = *(const float4*)&xr[ci];
            float4 w = *(const float4*)&wr_[ci];
            a0 += a.x * w.x;
            a1 += a.y * w.y;
            a2s += a.z * w.z;
            a3s += a.w * w.w;
        }
    }
    float v = leaky_((a0 + a1) + (a2s + a3s) + b1[f]);
    out[((size_t)bb * TT + t0 + tl) * FF + f] = v;
}

// ---------------- launch ----------------
extern "C" void kernel_launch(void* const* d_in, const int* in_sizes, int n_in,
                              void* d_out, int out_size) {
    const float* x        = (const float*)d_in[0];
    const float* enc_Wih  = (const float*)d_in[1];
    const float* enc_Whh  = (const float*)d_in[2];
    const float* enc_bih  = (const float*)d_in[3];
    const float* enc_bhh  = (const float*)d_in[4];
    const float* g1_Wih_f = (const float*)d_in[5];
    const float* g1_Whh_f = (const float*)d_in[6];
    const float* g1_bih_f = (const float*)d_in[7];
    const float* g1_bhh_f = (const float*)d_in[8];
    const float* g1_Wih_b = (const float*)d_in[9];
    const float* g1_Whh_b = (const float*)d_in[10];
    const float* g1_bih_b = (const float*)d_in[11];
    const float* g1_bhh_b = (const float*)d_in[12];
    const float* g2_Wih   = (const float*)d_in[13];
    const float* g2_Whh   = (const float*)d_in[14];
    const float* g2_bih   = (const float*)d_in[15];
    const float* g2_bhh   = (const float*)d_in[16];
    const float* w3       = (const float*)d_in[17];
    const float* b3       = (const float*)d_in[18];
    const float* w2       = (const float*)d_in[19];
    const float* b2       = (const float*)d_in[20];
    const float* w1       = (const float*)d_in[21];
    const float* b1       = (const float*)d_in[22];
    float* out = (float*)d_out;

    const int SMEM3 = (2 * 132 * 40 + 2 * 64 * 168) * 2;     // 64128 B
    const int SMEM2 = (2 * 132 * 72 + 4 * 128 * 24) * 2;     // 62592 B
    const int SMEMX = (2 * 128 * 72 + 2 * 96 * 72) * 2;      // 64512 B
    static bool attr_set = false;
    if (!attr_set) {
        cudaFuncSetAttribute(k_conv3_tc, cudaFuncAttributeMaxDynamicSharedMemorySize, SMEM3);
        cudaFuncSetAttribute(k_conv2_tc, cudaFuncAttributeMaxDynamicSharedMemorySize, SMEM2);
        cudaFuncSetAttribute(k_xp2_tc,  cudaFuncAttributeMaxDynamicSharedMemorySize, SMEMX);
        attr_set = true;
    }

    k_wprep<<<(16 * 64 * 160 + 16 * 128 * 320 + 255) / 256, 256>>>(w3, w2);
    k_enc_xp<<<(BB * TT * 48 + 255) / 256, 256>>>(x, enc_Wih, enc_bih);
    k_enc_rec<<<32, 128>>>(enc_Whh, enc_bhh);
    k_g1<<<256, 256>>>(g1_Wih_f, g1_Whh_f, g1_bih_f, g1_bhh_f,
                       g1_Wih_b, g1_Whh_b, g1_bih_b, g1_bhh_b);
    {
        dim3 g(BB * TT / 128, FF);
        k_xp2_tc<<<g, 256, SMEMX>>>(g2_Wih, g2_bih);
    }
    k_g2<<<256, 256>>>(g2_Whh, g2_bhh);
    {
        dim3 g(TT / 128, BB, FF);
        k_conv3_tc<<<g, 256, SMEM3>>>(b3);
        k_conv2_tc<<<g, 256, SMEM2>>>(b2);
    }
    {
        dim3 g(TT / 64, BB, FF);
        k_conv1<<<g, 64>>>(w1, b1, out);
    }
}